// round 16
// baseline (speedup 1.0000x reference)
#include <cuda_runtime.h>
#include <cuda_fp16.h>
#include <cstdint>

#define V 32768            // 32*32*32
#define CC 219             // real channels
#define CP 224             // padded channels (multiple of 32)

__device__ float g_x[CP * V];              // channels 128..223 used: cost(27), Cup(64), pad(5)
__device__ float g_y[CP * V];              // conv1 output (padded)
__device__ uint32_t g_wh[27 * 7 * 3584];   // conv1 weights half2-packed, 16B-seg swizzle
__device__ uint32_t g_wh2[27 * 7 * 3584];  // conv2 weights
__device__ uint32_t g_wu[8 * 13 * 8 * 1024]; // upsample weights per parity
__device__ const float* g_chan1[CP];       // conv1 per-channel base pointers
__device__ const float* g_chan2[CP];       // conv2 per-channel base pointers

__device__ __forceinline__ uint32_t smem_u32(const void* p) {
    uint32_t a;
    asm("{ .reg .u64 t; cvta.to.shared.u64 t, %1; cvt.u32.u64 %0, t; }" : "=r"(a) : "l"(p));
    return a;
}
__device__ __forceinline__ void cp_async16(uint32_t dst, const void* src) {
    asm volatile("cp.async.cg.shared.global [%0], [%1], 16;" :: "r"(dst), "l"(src));
}
#define CP_COMMIT() asm volatile("cp.async.commit_group;" ::: "memory")
#define CP_WAIT1()  asm volatile("cp.async.wait_group 1;" ::: "memory")

__device__ __forceinline__ void mma_f16(float d[4], const uint32_t a[4], const uint32_t b[2]) {
    asm volatile(
        "mma.sync.aligned.m16n8k16.row.col.f32.f16.f16.f32 "
        "{%0,%1,%2,%3}, {%4,%5,%6,%7}, {%8,%9}, {%0,%1,%2,%3};"
        : "+f"(d[0]), "+f"(d[1]), "+f"(d[2]), "+f"(d[3])
        : "r"(a[0]), "r"(a[1]), "r"(a[2]), "r"(a[3]), "r"(b[0]), "r"(b[1]));
}
__device__ __forceinline__ void ldsm_x4(uint32_t r[4], uint32_t addr) {
    asm volatile("ldmatrix.sync.aligned.m8n8.x4.shared.b16 {%0,%1,%2,%3}, [%4];"
                 : "=r"(r[0]), "=r"(r[1]), "=r"(r[2]), "=r"(r[3]) : "r"(addr));
}
__device__ __forceinline__ void ldsm_x2(uint32_t r[2], uint32_t addr) {
    asm volatile("ldmatrix.sync.aligned.m8n8.x2.shared.b16 {%0,%1}, [%2];"
                 : "=r"(r[0]), "=r"(r[1]) : "r"(addr));
}

// ======================= small kernels =======================
__global__ void pad_zero_kernel() {
    int i = blockIdx.x * 256 + threadIdx.x;      // over 5*V
    g_x[(size_t)CC * V + i] = 0.f;
    g_y[(size_t)CC * V + i] = 0.f;
}

__global__ void fill_chan_kernel(const float* __restrict__ tgt, const float* __restrict__ src) {
    int i = threadIdx.x;                         // 224 threads
    if (i >= CP) return;
    const float* p;
    if (i < 64)       p = tgt + (size_t)i * V;
    else if (i < 128) p = src + (size_t)(i - 64) * V;
    else              p = g_x + (size_t)i * V;   // cost + Cup + pad live in g_x
    g_chan1[i] = p;
    g_chan2[i] = g_y + (size_t)i * V;
}

// combined conv weight reorder (both convs in one launch): half2 pack + 16B-seg swizzle.
__global__ void reorder_wc_kernel(const float* __restrict__ w1, const float* __restrict__ w2) {
    int id = blockIdx.x * 256 + threadIdx.x;     // < 2 * 677376
    if (id >= 2 * 27 * 7 * 3584) return;
    int which = id >= 27 * 7 * 3584;
    int lid = id - which * 27 * 7 * 3584;
    const float* w = which ? w2 : w1;
    int blob = lid / 3584, r = lid % 3584;
    int tap = blob / 7, cib = blob % 7;
    int co = r >> 4, jj = r & 15;
    int wlog = (((jj >> 2) ^ ((co >> 1) & 3)) << 2) | (jj & 3);
    int ci0 = cib * 32 + 2 * wlog;
    float v0 = 0.f, v1 = 0.f;
    if (co < CC) {
        if (ci0 < CC)     v0 = w[((size_t)co * CC + ci0) * 27 + tap];
        if (ci0 + 1 < CC) v1 = w[((size_t)co * CC + ci0 + 1) * 27 + tap];
    }
    half2 h = __floats2half2_rn(v0, v1);
    if (which) g_wh2[lid] = *(uint32_t*)&h;
    else       g_wh[lid]  = *(uint32_t*)&h;
}

// upsample weight reorder: per parity class p, tap t -> (kz,ky,kx) of the 4x4x4 kernel.
__global__ void reorder_wu_kernel(const float* __restrict__ w) {
    int id = blockIdx.x * 256 + threadIdx.x;     // < 851968
    if (id >= 8 * 13 * 8 * 1024) return;
    int jj = id & 15;
    int t = id >> 4;
    int co = t & 63; t >>= 6;
    int tap = t & 7; t >>= 3;
    int cib = t % 13;
    int p = t / 13;
    int pz = p >> 2, py = (p >> 1) & 1, px = p & 1;
    int tz = tap >> 2, ty = (tap >> 1) & 1, tx = tap & 1;
    int kz = (1 - pz) + 2 * tz;
    int ky = (1 - py) + 2 * ty;
    int kx = (1 - px) + 2 * tx;
    int wlog = (((jj >> 2) ^ ((co >> 1) & 3)) << 2) | (jj & 3);
    int ci0 = cib * 32 + 2 * wlog;
    float v0 = 0.f, v1 = 0.f;
    if (ci0 < 411)     v0 = w[((size_t)ci0 * 64 + co) * 64 + kz * 16 + ky * 4 + kx];
    if (ci0 + 1 < 411) v1 = w[((size_t)(ci0 + 1) * 64 + co) * 64 + kz * 16 + ky * 4 + kx];
    half2 h = __floats2half2_rn(v0, v1);
    g_wu[id] = *(uint32_t*)&h;
}

// ======================= correlation volume (4 channels / iteration) =======================
__global__ void __launch_bounds__(256) corr_kernel(const float* __restrict__ tgt,
                                                   const float* __restrict__ src) {
    __shared__ float sp[3264];   // 4 x (4*6*34) patches
    int tid = threadIdx.x;
    int z0 = (blockIdx.x >> 3) * 2;
    int y0 = (blockIdx.x & 7) * 4;
    int tz = tid >> 7, ty = (tid >> 5) & 3, tx = tid & 31;
    int z = z0 + tz, y = y0 + ty;
    int p = (z << 10) + (y << 5) + tx;

    int poff[13]; bool pval[13]; int phalf[13];
#pragma unroll
    for (int k = 0; k < 13; k++) {
        int i = k * 256 + tid;
        int half = i / 816;
        int j = i - half * 816;
        int pz = j / 204, r = j % 204, py = r / 34, px = r % 34;
        int gz = z0 + pz - 1, gy = y0 + py - 1, gx = px - 1;
        pval[k] = (i < 3264) && ((unsigned)gz < 32u) && ((unsigned)gy < 32u) && ((unsigned)gx < 32u);
        poff[k] = (gz << 10) + (gy << 5) + gx;
        phalf[k] = half;
    }

    float acc[27];
#pragma unroll
    for (int d = 0; d < 27; d++) acc[d] = 0.f;

    for (int c = 0; c < 16; c++) {       // 16 iterations x 4 channels
        __syncthreads();
#pragma unroll
        for (int k = 0; k < 13; k++) {
            int i = k * 256 + tid;
            if (i < 3264) sp[i] = pval[k] ? src[(size_t)(4 * c + phalf[k]) * V + poff[k]] : 0.f;
        }
        __syncthreads();
        float t0 = tgt[(size_t)(4 * c) * V + p];
        float t1 = tgt[(size_t)(4 * c + 1) * V + p];
        float t2 = tgt[(size_t)(4 * c + 2) * V + p];
        float t3 = tgt[(size_t)(4 * c + 3) * V + p];
#pragma unroll
        for (int dz = 0; dz < 3; dz++)
#pragma unroll
            for (int dy = 0; dy < 3; dy++) {
                int base = ((tz + dz) * 6 + (ty + dy)) * 34 + tx;
#pragma unroll
                for (int q = 0; q < 3; q++)
                    acc[dz * 9 + dy * 3 + q] += t0 * sp[base + q] + t1 * sp[816 + base + q]
                                              + t2 * sp[1632 + base + q] + t3 * sp[2448 + base + q];
            }
    }
    const float inv = 1.f / 64.f;
#pragma unroll
    for (int d = 0; d < 27; d++) g_x[(size_t)(128 + d) * V + p] = acc[d] * inv;
}

// ======================= upsample as fp16 implicit GEMM (proven R13) =======================
__global__ void __launch_bounds__(256, 2) upsample_mma_kernel(const float* __restrict__ Cin) {
    extern __shared__ uint32_t smem32[];
    uint32_t* P = smem32;                    // 4896 words
    uint32_t sbase = smem_u32(smem32);
    const uint32_t PBYTE = 19584u;

    int tid = threadIdx.x, wid = tid >> 5, lane = tid & 31;
    int a = blockIdx.x >> 1, b0 = (blockIdx.x & 1) * 8;
    int par = blockIdx.y;
    int pz = par >> 2, py = (par >> 1) & 1, px = par & 1;

    int wm = wid >> 1, wn = wid & 1;
    int r4 = lane >> 2, c4 = lane & 3;
    int sub = lane >> 3, l7 = lane & 7;
    int a_lro = ((sub & 1) << 3) + l7;
    int a_sh = sub >> 1;
    int b_segbit = sub & 1;
    int b_ntoff = sub >> 1;
    uint32_t bco[2]; int bsw[2];
#pragma unroll
    for (int t2 = 0; t2 < 2; t2++) {
        int co = wn * 32 + (2 * t2 + b_ntoff) * 8 + l7;
        bco[t2] = (uint32_t)(co << 6);
        bsw[t2] = (co >> 1) & 3;
    }

    float acc[2][4][4];
#pragma unroll
    for (int i = 0; i < 2; i++)
#pragma unroll
        for (int j = 0; j < 4; j++)
#pragma unroll
            for (int k = 0; k < 4; k++) acc[i][j][k] = 0.f;

#define PREFETCH_U(s_, buf_) do { \
        int cib_ = (s_); \
        uint32_t dbase = sbase + PBYTE + (uint32_t)(buf_) * 32768u; \
        _Pragma("unroll") \
        for (int it = 0; it < 8; it++) { \
            int i = tid + it * 256; \
            int tl = i >> 8, rem = i & 255; \
            const uint32_t* src = g_wu + ((size_t)((par * 13 + cib_) * 8 + tl) << 10) + rem * 4; \
            cp_async16(dbase + (uint32_t)((tl << 12) + (rem << 4)), src); \
        } \
        CP_COMMIT(); \
    } while (0)

    PREFETCH_U(0, 0);
    PREFETCH_U(1, 1);

    for (int s = 0; s < 13; s++) {
        int buf = s & 1;
        {
            int cig0 = s * 32;
#pragma unroll 4
            for (int jj = 0; jj < 36; jj++) {
                int pp = wid + jj * 8;           // 0..287
                int wword = pp & 15;
                int rowslot = pp >> 4;           // 0..17
                int slot = rowslot / 9, ry = rowslot - slot * 9;
                int iz = a + pz - 1 + slot;
                int iy = b0 + py - 1 + ry;
                bool rowok = ((unsigned)iz < 16u) && ((unsigned)iy < 16u);
                int c0 = cig0 + 2 * wword;
                const float* s0 = Cin + (size_t)c0 * 4096 + (iz << 8) + (iy << 4);
                if (lane < 17) {
                    int ix = px - 1 + lane;
                    bool ok = rowok && ((unsigned)ix < 16u);
                    float v0 = (ok && c0 < 411) ? __ldg(s0 + ix) : 0.f;
                    float v1 = (ok && c0 + 1 < 411) ? __ldg(s0 + 4096 + ix) : 0.f;
                    half2 h = __floats2half2_rn(v0, v1);
                    int row = slot * 153 + ry * 17 + lane;
                    int st = (((wword >> 2) ^ ((row >> 1) & 3)) << 2) | (wword & 3);
                    P[row * 16 + st] = *(uint32_t*)&h;
                }
            }
        }
        CP_WAIT1();
        __syncthreads();

#pragma unroll
        for (int tap = 0; tap < 8; tap++) {
            int tz = tap >> 2, ty = (tap >> 1) & 1, tx = tap & 1;
            int vb0 = (1 - tz) * 153 + (2 * wm + 1 - ty) * 17 + (1 - tx);
            uint32_t Bbb = sbase + PBYTE + (uint32_t)buf * 32768u + (uint32_t)tap * 4096u;

#pragma unroll
            for (int ks = 0; ks < 2; ks++) {
                uint32_t af[2][4];
#pragma unroll
                for (int mt = 0; mt < 2; mt++) {
                    int v = vb0 + mt * 17 + a_lro;
                    uint32_t ad = sbase + (uint32_t)(v << 6)
                                + (uint32_t)((((ks << 1) + a_sh) ^ ((v >> 1) & 3)) << 4);
                    ldsm_x4(af[mt], ad);
                }
                uint32_t bf[4][2];
#pragma unroll
                for (int t2 = 0; t2 < 2; t2++) {
                    uint32_t r[4];
                    uint32_t ad = Bbb + bco[t2] + (uint32_t)((((ks << 1) + b_segbit) ^ bsw[t2]) << 4);
                    ldsm_x4(r, ad);
                    bf[2 * t2][0] = r[0]; bf[2 * t2][1] = r[1];
                    bf[2 * t2 + 1][0] = r[2]; bf[2 * t2 + 1][1] = r[3];
                }
#pragma unroll
                for (int mt = 0; mt < 2; mt++)
#pragma unroll
                    for (int nt = 0; nt < 4; nt++)
                        mma_f16(acc[mt][nt], af[mt], bf[nt]);
            }
        }
        __syncthreads();
        if (s + 2 < 13) PREFETCH_U(s + 2, buf);
    }

    int oz = 2 * a + pz;
#pragma unroll
    for (int mt = 0; mt < 2; mt++) {
        int bl = 2 * wm + mt;
        int oy = 2 * (b0 + bl) + py;
        int base = (oz << 10) + (oy << 5) + px;
#pragma unroll
        for (int nt = 0; nt < 4; nt++) {
            int co = wn * 32 + (nt << 3) + (c4 << 1);
            size_t ch0 = (size_t)(155 + co) * V;
            size_t ch1 = (size_t)(156 + co) * V;
            int o1 = base + 2 * r4, o2 = base + 2 * (r4 + 8);
            g_x[ch0 + o1] = acc[mt][nt][0];
            g_x[ch0 + o2] = acc[mt][nt][2];
            g_x[ch1 + o1] = acc[mt][nt][1];
            g_x[ch1 + o2] = acc[mt][nt][3];
        }
    }
}

// ======================= fused instance norm: stats + normalize + leaky ====
__global__ void __launch_bounds__(256) instnorm_kernel(float* __restrict__ x) {
    int ch = blockIdx.x;
    float4* p4 = (float4*)(x + (size_t)ch * V);
    float s = 0.f, s2 = 0.f;
    for (int i = threadIdx.x; i < V / 4; i += 256) {
        float4 v = p4[i];
        s += v.x + v.y + v.z + v.w;
        s2 += v.x * v.x + v.y * v.y + v.z * v.z + v.w * v.w;
    }
#pragma unroll
    for (int o = 16; o; o >>= 1) {
        s += __shfl_down_sync(0xffffffffu, s, o);
        s2 += __shfl_down_sync(0xffffffffu, s2, o);
    }
    __shared__ float a[8], b[8];
    __shared__ float smr[2];
    int wp = threadIdx.x >> 5, ln = threadIdx.x & 31;
    if (ln == 0) { a[wp] = s; b[wp] = s2; }
    __syncthreads();
    if (threadIdx.x < 8) {
        s = a[threadIdx.x]; s2 = b[threadIdx.x];
#pragma unroll
        for (int o = 4; o; o >>= 1) {
            s += __shfl_down_sync(0xffu, s, o);
            s2 += __shfl_down_sync(0xffu, s2, o);
        }
        if (threadIdx.x == 0) {
            float m = s * (1.f / V);
            float var = s2 * (1.f / V) - m * m;
            smr[0] = m;
            smr[1] = rsqrtf(var + 1e-5f);
        }
    }
    __syncthreads();
    float m = smr[0], r = smr[1];
    for (int i = threadIdx.x; i < V / 4; i += 256) {
        float4 v = p4[i];
        v.x = (v.x - m) * r; v.x = v.x >= 0.f ? v.x : 0.1f * v.x;
        v.y = (v.y - m) * r; v.y = v.y >= 0.f ? v.y : 0.1f * v.y;
        v.z = (v.z - m) * r; v.z = v.z >= 0.f ? v.z : 0.1f * v.z;
        v.w = (v.w - m) * r; v.w = v.w >= 0.f ? v.w : 0.1f * v.w;
        p4[i] = v;
    }
}

// ======================= fp16 HMMA conv3x3x3: per-channel pointer table ========
__global__ void __launch_bounds__(256, 2) conv3_mma_kernel(const float* const* __restrict__ chan,
                                                           const uint32_t* __restrict__ wsrc,
                                                           const float* __restrict__ bias,
                                                           float* __restrict__ out) {
    extern __shared__ uint32_t smem32[];
    uint32_t* P = smem32;                    // 9792 words
    uint32_t sbase = smem_u32(smem32);
    const uint32_t BBYTE = 9792u * 4u;       // byte offset of B buffers (2 x 21504 B)

    int tid = threadIdx.x, wid = tid >> 5, lane = tid & 31;
    int z = blockIdx.x >> 3, yt = blockIdx.x & 7;
    int y0 = yt * 4;
    int co0 = blockIdx.y * 112;

    int wm = wid >> 1, wn = wid & 1;         // wm = local y row
    int r4 = lane >> 2, c4 = lane & 3;

    int sub = lane >> 3, l7 = lane & 7;
    int a_lro = ((sub & 1) << 3) + l7;
    int a_sh = sub >> 1;
    int b_segbit = sub & 1;
    int b_ntoff = sub >> 1;
    uint32_t bco[4]; int bsw[4];
#pragma unroll
    for (int t = 0; t < 3; t++) {
        int co = wn * 56 + (2 * t + b_ntoff) * 8 + l7;
        bco[t] = (uint32_t)(co << 6);
        bsw[t] = (co >> 1) & 3;
    }
    {
        int co = wn * 56 + 48 + l7;
        bco[3] = (uint32_t)(co << 6);
        bsw[3] = (co >> 1) & 3;
    }

    float acc[2][7][4];
#pragma unroll
    for (int a = 0; a < 2; a++)
#pragma unroll
        for (int b = 0; b < 7; b++)
#pragma unroll
            for (int c = 0; c < 4; c++) acc[a][b][c] = 0.f;

#define PREFETCH_GRP(s_, buf_) do { \
        int cib_ = (s_) / 9, grp_ = (s_) % 9; \
        uint32_t dbase = sbase + BBYTE + (uint32_t)(buf_) * 21504u; \
        _Pragma("unroll") \
        for (int it = 0; it < 6; it++) { \
            int i = tid + it * 256; \
            if (i < 1344) { \
                int tl = i / 448, rem = i - tl * 448; \
                const uint32_t* src = wsrc + (size_t)((grp_ * 3 + tl) * 7 + cib_) * 3584 + co0 * 16 + rem * 4; \
                cp_async16(dbase + (uint32_t)(tl * 7168 + rem * 16), src); \
            } \
        } \
        CP_COMMIT(); \
    } while (0)

    PREFETCH_GRP(0, 0);
    PREFETCH_GRP(1, 1);

    for (int s = 0; s < 63; s++) {
        int cib = s / 9, grp = s - cib * 9;
        int buf = s & 1;

        if (grp == 0) {
            int cig0 = cib * 32;
#pragma unroll 4
            for (int jj = 0; jj < 36; jj++) {
                int p = wid + jj * 8;        // 0..287
                int wword = p & 15;
                int rowid = p >> 4;          // 0..17 (3z x 6y)
                int pz = rowid / 6, py = rowid - pz * 6;
                int gz = z + pz - 1, gy = y0 + py - 1;
                bool rowok = ((unsigned)gz < 32u) && ((unsigned)gy < 32u);
                int c0 = cig0 + 2 * wword;
                int voff = (gz << 10) + (gy << 5);
                const float* sA = chan[c0] + voff;
                const float* sB = chan[c0 + 1] + voff;
#pragma unroll
                for (int q = 0; q < 2; q++) {
                    int px = lane + q * 32;
                    if (px < 34) {
                        int gx = px - 1;
                        bool ok = rowok && ((unsigned)gx < 32u);
                        float v0 = ok ? __ldg(sA + gx) : 0.f;
                        float v1 = ok ? __ldg(sB + gx) : 0.f;
                        half2 h = __floats2half2_rn(v0, v1);
                        int voxel = rowid * 34 + px;
                        int st = (((wword >> 2) ^ ((voxel >> 1) & 3)) << 2) | (wword & 3);
                        P[voxel * 16 + st] = *(uint32_t*)&h;
                    }
                }
            }
        }

        CP_WAIT1();
        __syncthreads();      // B(buf) ready + patch visible

#pragma unroll
        for (int t = 0; t < 3; t++) {
            int tap = grp * 3 + t;
            int dz = tap / 9, rem = tap - dz * 9;
            int dy = rem / 3, dx = rem - dy * 3;
            int vb = (dz * 6 + wm + dy) * 34 + dx;
            uint32_t Bbb = sbase + BBYTE + (uint32_t)buf * 21504u + (uint32_t)t * 7168u;

#pragma unroll
            for (int ks = 0; ks < 2; ks++) {
                uint32_t af[2][4];
#pragma unroll
                for (int mt = 0; mt < 2; mt++) {
                    int v = vb + a_lro + (mt << 4);
                    uint32_t ad = sbase + (uint32_t)(v << 6)
                                + (uint32_t)((((ks << 1) + a_sh) ^ ((v >> 1) & 3)) << 4);
                    ldsm_x4(af[mt], ad);
                }
                uint32_t bf[7][2];
#pragma unroll
                for (int t2 = 0; t2 < 3; t2++) {
                    uint32_t r[4];
                    uint32_t ad = Bbb + bco[t2] + (uint32_t)((((ks << 1) + b_segbit) ^ bsw[t2]) << 4);
                    ldsm_x4(r, ad);
                    bf[2 * t2][0] = r[0]; bf[2 * t2][1] = r[1];
                    bf[2 * t2 + 1][0] = r[2]; bf[2 * t2 + 1][1] = r[3];
                }
                {
                    uint32_t r2[2];
                    uint32_t ad = Bbb + bco[3] + (uint32_t)((((ks << 1) + b_segbit) ^ bsw[3]) << 4);
                    ldsm_x2(r2, ad);
                    bf[6][0] = r2[0]; bf[6][1] = r2[1];
                }
#pragma unroll
                for (int mt = 0; mt < 2; mt++)
#pragma unroll
                    for (int nt = 0; nt < 7; nt++)
                        mma_f16(acc[mt][nt], af[mt], bf[nt]);
            }
        }

        __syncthreads();
        if (s + 2 < 63) PREFETCH_GRP(s + 2, buf);
    }

    // ---- epilogue ----
    int yg = y0 + wm;
#pragma unroll
    for (int mt = 0; mt < 2; mt++) {
        int x1 = (mt << 4) + r4;
        int pos = (z << 10) + (yg << 5) + x1;
#pragma unroll
        for (int nt = 0; nt < 7; nt++) {
            int c = co0 + wn * 56 + (nt << 3) + (c4 << 1);
            if (c < CC) {
                float bb = bias[c];
                out[(size_t)c * V + pos] = acc[mt][nt][0] + bb;
                out[(size_t)c * V + pos + 8] = acc[mt][nt][2] + bb;
            }
            if (c + 1 < CC) {
                float bb = bias[c + 1];
                out[(size_t)(c + 1) * V + pos] = acc[mt][nt][1] + bb;
                out[(size_t)(c + 1) * V + pos + 8] = acc[mt][nt][3] + bb;
            }
        }
    }
}

// ======================= final 3-channel conv (fp32, 4 channels / iteration) =======================
__global__ void __launch_bounds__(256) conv_out_kernel(const float* __restrict__ in,
                                                       const float* __restrict__ w,
                                                       const float* __restrict__ bias,
                                                       float* __restrict__ out) {
    __shared__ float sp[3264];   // 4 x (4*6*34)
    __shared__ float sw[324];    // 4 x (3 co x 27)
    int tid = threadIdx.x;
    int z0 = (blockIdx.x >> 3) * 2;
    int y0 = (blockIdx.x & 7) * 4;
    int tz = tid >> 7, ty = (tid >> 5) & 3, tx = tid & 31;

    int poff[13]; bool pval[13]; int phalf[13];
#pragma unroll
    for (int k = 0; k < 13; k++) {
        int i = k * 256 + tid;
        int half = i / 816;
        int j = i - half * 816;
        int pz = j / 204, r = j % 204, py = r / 34, px = r % 34;
        int gz = z0 + pz - 1, gy = y0 + py - 1, gx = px - 1;
        pval[k] = (i < 3264) && ((unsigned)gz < 32u) && ((unsigned)gy < 32u) && ((unsigned)gx < 32u);
        poff[k] = (gz << 10) + (gy << 5) + gx;
        phalf[k] = half;
    }

    float acc[3] = {0.f, 0.f, 0.f};
    for (int c = 0; c < 55; c++) {            // quads (4c..4c+3), ci>=219 padded to 0
        __syncthreads();
#pragma unroll
        for (int k = 0; k < 13; k++) {
            int i = k * 256 + tid;
            if (i < 3264) {
                int ch = 4 * c + phalf[k];
                sp[i] = (pval[k] && ch < CC) ? in[(size_t)ch * V + poff[k]] : 0.f;
            }
        }
#pragma unroll
        for (int wpass = 0; wpass < 2; wpass++) {
            int i = tid + wpass * 256;
            if (i < 324) {
                int half = i / 81;
                int t = i - half * 81;
                int ch = 4 * c + half;
                sw[i] = (ch < CC) ? w[((size_t)(t / 27) * CC + ch) * 27 + (t % 27)] : 0.f;
            }
        }
        __syncthreads();
#pragma unroll
        for (int kz = 0; kz < 3; kz++)
#pragma unroll
            for (int ky = 0; ky < 3; ky++) {
                int base = ((tz + kz) * 6 + (ty + ky)) * 34 + tx;
#pragma unroll
                for (int kx = 0; kx < 3; kx++) {
                    int wt = (kz * 3 + ky) * 3 + kx;
                    float v0 = sp[base + kx];
                    float v1 = sp[816 + base + kx];
                    float v2 = sp[1632 + base + kx];
                    float v3 = sp[2448 + base + kx];
#pragma unroll
                    for (int co = 0; co < 3; co++)
                        acc[co] += sw[co * 27 + wt] * v0 + sw[81 + co * 27 + wt] * v1
                                 + sw[162 + co * 27 + wt] * v2 + sw[243 + co * 27 + wt] * v3;
                }
            }
    }
    int p = ((z0 + tz) << 10) + ((y0 + ty) << 5) + tx;
#pragma unroll
    for (int co = 0; co < 3; co++) out[(size_t)co * V + p] = acc[co] + bias[co];
}

// ======================= launch =======================
extern "C" void kernel_launch(void* const* d_in, const int* in_sizes, int n_in,
                              void* d_out, int out_size) {
    (void)in_sizes; (void)n_in; (void)out_size;
    const float* src   = (const float*)d_in[0];
    const float* tgt   = (const float*)d_in[1];
    const float* C     = (const float*)d_in[2];
    const float* up_w  = (const float*)d_in[3];
    const float* c1_w  = (const float*)d_in[5];
    const float* c1_b  = (const float*)d_in[6];
    const float* c2_w  = (const float*)d_in[7];
    const float* c2_b  = (const float*)d_in[8];
    const float* out_w = (const float*)d_in[9];
    const float* out_b = (const float*)d_in[10];
    float* dout = (float*)d_out;

    float *gx = nullptr, *gy = nullptr;
    const float **chan1 = nullptr, **chan2 = nullptr;
    uint32_t *wh = nullptr, *wh2 = nullptr;
    cudaGetSymbolAddress((void**)&gx, g_x);
    cudaGetSymbolAddress((void**)&gy, g_y);
    cudaGetSymbolAddress((void**)&chan1, g_chan1);
    cudaGetSymbolAddress((void**)&chan2, g_chan2);
    cudaGetSymbolAddress((void**)&wh, g_wh);
    cudaGetSymbolAddress((void**)&wh2, g_wh2);

    const int CONV_SMEM = 82176;   // (9792 + 2*5376) uint32 words
    const int UP_SMEM = 85120;     // (4896 + 2*8192) uint32 words
    cudaFuncSetAttribute(conv3_mma_kernel, cudaFuncAttributeMaxDynamicSharedMemorySize, CONV_SMEM);
    cudaFuncSetAttribute(upsample_mma_kernel, cudaFuncAttributeMaxDynamicSharedMemorySize, UP_SMEM);

    // Stage 1: build cost/Cup in g_x (tgt/src read in-place via pointer table)
    pad_zero_kernel<<<640, 256>>>();
    fill_chan_kernel<<<1, 256>>>(tgt, src);
    reorder_wc_kernel<<<5292, 256>>>(c1_w, c2_w);
    reorder_wu_kernel<<<3328, 256>>>(up_w);
    corr_kernel<<<128, 256>>>(tgt, src);
    upsample_mma_kernel<<<dim3(32, 8), 256, UP_SMEM>>>(C);

    // IN + leaky on Cup (channels 155..218 of g_x)
    instnorm_kernel<<<64, 256>>>(gx + (size_t)155 * V);

    // conv1 (fp16 HMMA, pointer-table input) + IN + leaky
    conv3_mma_kernel<<<dim3(256, 2), 256, CONV_SMEM>>>(chan1, wh, c1_b, gy);
    instnorm_kernel<<<CC, 256>>>(gy);

    // conv2 + IN + leaky -> Cn in d_out[0 .. 219*V)
    conv3_mma_kernel<<<dim3(256, 2), 256, CONV_SMEM>>>(chan2, wh2, c2_b, dout);
    instnorm_kernel<<<CC, 256>>>(dout);

    // output conv -> d_out[219*V .. 222*V)
    conv_out_kernel<<<128, 256>>>(dout, out_w, out_b, dout + (size_t)CC * V);
}

// round 17
// speedup vs baseline: 1.0518x; 1.0518x over previous
#include <cuda_runtime.h>
#include <cuda_fp16.h>
#include <cstdint>

#define V 32768            // 32*32*32
#define CC 219             // real channels
#define CP 224             // padded channels (multiple of 32)

__device__ float g_x[CP * V];              // concat input [tgt(64), src(64), cost(27), Cup(64), pad(5)=0]
__device__ float g_y[CP * V];              // conv1 output (padded)
__device__ uint32_t g_wh[27 * 7 * 3584];   // conv1 weights half2-packed, 16B-seg swizzle
__device__ uint32_t g_wh2[27 * 7 * 3584];  // conv2 weights
__device__ uint32_t g_wu[8 * 13 * 8 * 1024]; // upsample weights per parity

__device__ __forceinline__ uint32_t smem_u32(const void* p) {
    uint32_t a;
    asm("{ .reg .u64 t; cvta.to.shared.u64 t, %1; cvt.u32.u64 %0, t; }" : "=r"(a) : "l"(p));
    return a;
}
__device__ __forceinline__ void cp_async16(uint32_t dst, const void* src) {
    asm volatile("cp.async.cg.shared.global [%0], [%1], 16;" :: "r"(dst), "l"(src));
}
#define CP_COMMIT() asm volatile("cp.async.commit_group;" ::: "memory")
#define CP_WAIT1()  asm volatile("cp.async.wait_group 1;" ::: "memory")

__device__ __forceinline__ void mma_f16(float d[4], const uint32_t a[4], const uint32_t b[2]) {
    asm volatile(
        "mma.sync.aligned.m16n8k16.row.col.f32.f16.f16.f32 "
        "{%0,%1,%2,%3}, {%4,%5,%6,%7}, {%8,%9}, {%0,%1,%2,%3};"
        : "+f"(d[0]), "+f"(d[1]), "+f"(d[2]), "+f"(d[3])
        : "r"(a[0]), "r"(a[1]), "r"(a[2]), "r"(a[3]), "r"(b[0]), "r"(b[1]));
}
__device__ __forceinline__ void ldsm_x4(uint32_t r[4], uint32_t addr) {
    asm volatile("ldmatrix.sync.aligned.m8n8.x4.shared.b16 {%0,%1,%2,%3}, [%4];"
                 : "=r"(r[0]), "=r"(r[1]), "=r"(r[2]), "=r"(r[3]) : "r"(addr));
}
__device__ __forceinline__ void ldsm_x2(uint32_t r[2], uint32_t addr) {
    asm volatile("ldmatrix.sync.aligned.m8n8.x2.shared.b16 {%0,%1}, [%2];"
                 : "=r"(r[0]), "=r"(r[1]) : "r"(addr));
}

// ======================= small kernels =======================
__global__ void pad_zero_kernel() {
    int i = blockIdx.x * 256 + threadIdx.x;      // over 5*V
    g_x[(size_t)CC * V + i] = 0.f;
    g_y[(size_t)CC * V + i] = 0.f;
}

__global__ void copy_kernel(const float* __restrict__ tgt, const float* __restrict__ src) {
    int i = blockIdx.x * 256 + threadIdx.x;   // over 64*V/4 float4
    float4* dx = (float4*)g_x;
    dx[i] = ((const float4*)tgt)[i];
    dx[(64 * V) / 4 + i] = ((const float4*)src)[i];
}

// combined conv weight reorder (both convs in one launch): half2 pack + 16B-seg swizzle.
__global__ void reorder_wc_kernel(const float* __restrict__ w1, const float* __restrict__ w2) {
    int id = blockIdx.x * 256 + threadIdx.x;     // < 2 * 677376
    if (id >= 2 * 27 * 7 * 3584) return;
    int which = id >= 27 * 7 * 3584;
    int lid = id - which * 27 * 7 * 3584;
    const float* w = which ? w2 : w1;
    int blob = lid / 3584, r = lid % 3584;
    int tap = blob / 7, cib = blob % 7;
    int co = r >> 4, jj = r & 15;
    int wlog = (((jj >> 2) ^ ((co >> 1) & 3)) << 2) | (jj & 3);
    int ci0 = cib * 32 + 2 * wlog;
    float v0 = 0.f, v1 = 0.f;
    if (co < CC) {
        if (ci0 < CC)     v0 = w[((size_t)co * CC + ci0) * 27 + tap];
        if (ci0 + 1 < CC) v1 = w[((size_t)co * CC + ci0 + 1) * 27 + tap];
    }
    half2 h = __floats2half2_rn(v0, v1);
    if (which) g_wh2[lid] = *(uint32_t*)&h;
    else       g_wh[lid]  = *(uint32_t*)&h;
}

// upsample weight reorder: per parity class p, tap t -> (kz,ky,kx) of the 4x4x4 kernel.
__global__ void reorder_wu_kernel(const float* __restrict__ w) {
    int id = blockIdx.x * 256 + threadIdx.x;     // < 851968
    if (id >= 8 * 13 * 8 * 1024) return;
    int jj = id & 15;
    int t = id >> 4;
    int co = t & 63; t >>= 6;
    int tap = t & 7; t >>= 3;
    int cib = t % 13;
    int p = t / 13;
    int pz = p >> 2, py = (p >> 1) & 1, px = p & 1;
    int tz = tap >> 2, ty = (tap >> 1) & 1, tx = tap & 1;
    int kz = (1 - pz) + 2 * tz;
    int ky = (1 - py) + 2 * ty;
    int kx = (1 - px) + 2 * tx;
    int wlog = (((jj >> 2) ^ ((co >> 1) & 3)) << 2) | (jj & 3);
    int ci0 = cib * 32 + 2 * wlog;
    float v0 = 0.f, v1 = 0.f;
    if (ci0 < 411)     v0 = w[((size_t)ci0 * 64 + co) * 64 + kz * 16 + ky * 4 + kx];
    if (ci0 + 1 < 411) v1 = w[((size_t)(ci0 + 1) * 64 + co) * 64 + kz * 16 + ky * 4 + kx];
    half2 h = __floats2half2_rn(v0, v1);
    g_wu[id] = *(uint32_t*)&h;
}

// ======================= correlation volume (4 channels / iteration) =======================
__global__ void __launch_bounds__(256) corr_kernel(const float* __restrict__ tgt,
                                                   const float* __restrict__ src) {
    __shared__ float sp[3264];   // 4 x (4*6*34) patches
    int tid = threadIdx.x;
    int z0 = (blockIdx.x >> 3) * 2;
    int y0 = (blockIdx.x & 7) * 4;
    int tz = tid >> 7, ty = (tid >> 5) & 3, tx = tid & 31;
    int z = z0 + tz, y = y0 + ty;
    int p = (z << 10) + (y << 5) + tx;

    int poff[13]; bool pval[13]; int phalf[13];
#pragma unroll
    for (int k = 0; k < 13; k++) {
        int i = k * 256 + tid;
        int half = i / 816;
        int j = i - half * 816;
        int pz = j / 204, r = j % 204, py = r / 34, px = r % 34;
        int gz = z0 + pz - 1, gy = y0 + py - 1, gx = px - 1;
        pval[k] = (i < 3264) && ((unsigned)gz < 32u) && ((unsigned)gy < 32u) && ((unsigned)gx < 32u);
        poff[k] = (gz << 10) + (gy << 5) + gx;
        phalf[k] = half;
    }

    float acc[27];
#pragma unroll
    for (int d = 0; d < 27; d++) acc[d] = 0.f;

    for (int c = 0; c < 16; c++) {       // 16 iterations x 4 channels
        __syncthreads();
#pragma unroll
        for (int k = 0; k < 13; k++) {
            int i = k * 256 + tid;
            if (i < 3264) sp[i] = pval[k] ? src[(size_t)(4 * c + phalf[k]) * V + poff[k]] : 0.f;
        }
        __syncthreads();
        float t0 = tgt[(size_t)(4 * c) * V + p];
        float t1 = tgt[(size_t)(4 * c + 1) * V + p];
        float t2 = tgt[(size_t)(4 * c + 2) * V + p];
        float t3 = tgt[(size_t)(4 * c + 3) * V + p];
#pragma unroll
        for (int dz = 0; dz < 3; dz++)
#pragma unroll
            for (int dy = 0; dy < 3; dy++) {
                int base = ((tz + dz) * 6 + (ty + dy)) * 34 + tx;
#pragma unroll
                for (int q = 0; q < 3; q++)
                    acc[dz * 9 + dy * 3 + q] += t0 * sp[base + q] + t1 * sp[816 + base + q]
                                              + t2 * sp[1632 + base + q] + t3 * sp[2448 + base + q];
            }
    }
    const float inv = 1.f / 64.f;
#pragma unroll
    for (int d = 0; d < 27; d++) g_x[(size_t)(128 + d) * V + p] = acc[d] * inv;
}

// ======================= upsample as fp16 implicit GEMM (proven R13) =======================
__global__ void __launch_bounds__(256, 2) upsample_mma_kernel(const float* __restrict__ Cin) {
    extern __shared__ uint32_t smem32[];
    uint32_t* P = smem32;                    // 4896 words
    uint32_t sbase = smem_u32(smem32);
    const uint32_t PBYTE = 19584u;

    int tid = threadIdx.x, wid = tid >> 5, lane = tid & 31;
    int a = blockIdx.x >> 1, b0 = (blockIdx.x & 1) * 8;
    int par = blockIdx.y;
    int pz = par >> 2, py = (par >> 1) & 1, px = par & 1;

    int wm = wid >> 1, wn = wid & 1;
    int r4 = lane >> 2, c4 = lane & 3;
    int sub = lane >> 3, l7 = lane & 7;
    int a_lro = ((sub & 1) << 3) + l7;
    int a_sh = sub >> 1;
    int b_segbit = sub & 1;
    int b_ntoff = sub >> 1;
    uint32_t bco[2]; int bsw[2];
#pragma unroll
    for (int t2 = 0; t2 < 2; t2++) {
        int co = wn * 32 + (2 * t2 + b_ntoff) * 8 + l7;
        bco[t2] = (uint32_t)(co << 6);
        bsw[t2] = (co >> 1) & 3;
    }

    float acc[2][4][4];
#pragma unroll
    for (int i = 0; i < 2; i++)
#pragma unroll
        for (int j = 0; j < 4; j++)
#pragma unroll
            for (int k = 0; k < 4; k++) acc[i][j][k] = 0.f;

#define PREFETCH_U(s_, buf_) do { \
        int cib_ = (s_); \
        uint32_t dbase = sbase + PBYTE + (uint32_t)(buf_) * 32768u; \
        _Pragma("unroll") \
        for (int it = 0; it < 8; it++) { \
            int i = tid + it * 256; \
            int tl = i >> 8, rem = i & 255; \
            const uint32_t* src = g_wu + ((size_t)((par * 13 + cib_) * 8 + tl) << 10) + rem * 4; \
            cp_async16(dbase + (uint32_t)((tl << 12) + (rem << 4)), src); \
        } \
        CP_COMMIT(); \
    } while (0)

    PREFETCH_U(0, 0);
    PREFETCH_U(1, 1);

    for (int s = 0; s < 13; s++) {
        int buf = s & 1;
        {
            int cig0 = s * 32;
#pragma unroll 4
            for (int jj = 0; jj < 36; jj++) {
                int pp = wid + jj * 8;           // 0..287
                int wword = pp & 15;
                int rowslot = pp >> 4;           // 0..17
                int slot = rowslot / 9, ry = rowslot - slot * 9;
                int iz = a + pz - 1 + slot;
                int iy = b0 + py - 1 + ry;
                bool rowok = ((unsigned)iz < 16u) && ((unsigned)iy < 16u);
                int c0 = cig0 + 2 * wword;
                const float* s0 = Cin + (size_t)c0 * 4096 + (iz << 8) + (iy << 4);
                if (lane < 17) {
                    int ix = px - 1 + lane;
                    bool ok = rowok && ((unsigned)ix < 16u);
                    float v0 = (ok && c0 < 411) ? __ldg(s0 + ix) : 0.f;
                    float v1 = (ok && c0 + 1 < 411) ? __ldg(s0 + 4096 + ix) : 0.f;
                    half2 h = __floats2half2_rn(v0, v1);
                    int row = slot * 153 + ry * 17 + lane;
                    int st = (((wword >> 2) ^ ((row >> 1) & 3)) << 2) | (wword & 3);
                    P[row * 16 + st] = *(uint32_t*)&h;
                }
            }
        }
        CP_WAIT1();
        __syncthreads();

#pragma unroll
        for (int tap = 0; tap < 8; tap++) {
            int tz = tap >> 2, ty = (tap >> 1) & 1, tx = tap & 1;
            int vb0 = (1 - tz) * 153 + (2 * wm + 1 - ty) * 17 + (1 - tx);
            uint32_t Bbb = sbase + PBYTE + (uint32_t)buf * 32768u + (uint32_t)tap * 4096u;

#pragma unroll
            for (int ks = 0; ks < 2; ks++) {
                uint32_t af[2][4];
#pragma unroll
                for (int mt = 0; mt < 2; mt++) {
                    int v = vb0 + mt * 17 + a_lro;
                    uint32_t ad = sbase + (uint32_t)(v << 6)
                                + (uint32_t)((((ks << 1) + a_sh) ^ ((v >> 1) & 3)) << 4);
                    ldsm_x4(af[mt], ad);
                }
                uint32_t bf[4][2];
#pragma unroll
                for (int t2 = 0; t2 < 2; t2++) {
                    uint32_t r[4];
                    uint32_t ad = Bbb + bco[t2] + (uint32_t)((((ks << 1) + b_segbit) ^ bsw[t2]) << 4);
                    ldsm_x4(r, ad);
                    bf[2 * t2][0] = r[0]; bf[2 * t2][1] = r[1];
                    bf[2 * t2 + 1][0] = r[2]; bf[2 * t2 + 1][1] = r[3];
                }
#pragma unroll
                for (int mt = 0; mt < 2; mt++)
#pragma unroll
                    for (int nt = 0; nt < 4; nt++)
                        mma_f16(acc[mt][nt], af[mt], bf[nt]);
            }
        }
        __syncthreads();
        if (s + 2 < 13) PREFETCH_U(s + 2, buf);
    }

    int oz = 2 * a + pz;
#pragma unroll
    for (int mt = 0; mt < 2; mt++) {
        int bl = 2 * wm + mt;
        int oy = 2 * (b0 + bl) + py;
        int base = (oz << 10) + (oy << 5) + px;
#pragma unroll
        for (int nt = 0; nt < 4; nt++) {
            int co = wn * 32 + (nt << 3) + (c4 << 1);
            size_t ch0 = (size_t)(155 + co) * V;
            size_t ch1 = (size_t)(156 + co) * V;
            int o1 = base + 2 * r4, o2 = base + 2 * (r4 + 8);
            g_x[ch0 + o1] = acc[mt][nt][0];
            g_x[ch0 + o2] = acc[mt][nt][2];
            g_x[ch1 + o1] = acc[mt][nt][1];
            g_x[ch1 + o2] = acc[mt][nt][3];
        }
    }
}

// ======================= fused instance norm: stats + normalize + leaky ====
__global__ void __launch_bounds__(256) instnorm_kernel(float* __restrict__ x) {
    int ch = blockIdx.x;
    float4* p4 = (float4*)(x + (size_t)ch * V);
    float s = 0.f, s2 = 0.f;
    for (int i = threadIdx.x; i < V / 4; i += 256) {
        float4 v = p4[i];
        s += v.x + v.y + v.z + v.w;
        s2 += v.x * v.x + v.y * v.y + v.z * v.z + v.w * v.w;
    }
#pragma unroll
    for (int o = 16; o; o >>= 1) {
        s += __shfl_down_sync(0xffffffffu, s, o);
        s2 += __shfl_down_sync(0xffffffffu, s2, o);
    }
    __shared__ float a[8], b[8];
    __shared__ float smr[2];
    int wp = threadIdx.x >> 5, ln = threadIdx.x & 31;
    if (ln == 0) { a[wp] = s; b[wp] = s2; }
    __syncthreads();
    if (threadIdx.x < 8) {
        s = a[threadIdx.x]; s2 = b[threadIdx.x];
#pragma unroll
        for (int o = 4; o; o >>= 1) {
            s += __shfl_down_sync(0xffu, s, o);
            s2 += __shfl_down_sync(0xffu, s2, o);
        }
        if (threadIdx.x == 0) {
            float m = s * (1.f / V);
            float var = s2 * (1.f / V) - m * m;
            smr[0] = m;
            smr[1] = rsqrtf(var + 1e-5f);
        }
    }
    __syncthreads();
    float m = smr[0], r = smr[1];
    for (int i = threadIdx.x; i < V / 4; i += 256) {
        float4 v = p4[i];
        v.x = (v.x - m) * r; v.x = v.x >= 0.f ? v.x : 0.1f * v.x;
        v.y = (v.y - m) * r; v.y = v.y >= 0.f ? v.y : 0.1f * v.y;
        v.z = (v.z - m) * r; v.z = v.z >= 0.f ? v.z : 0.1f * v.z;
        v.w = (v.w - m) * r; v.w = v.w >= 0.f ? v.w : 0.1f * v.w;
        p4[i] = v;
    }
}

// ======================= fp16 HMMA conv3x3x3: 2 CTAs/SM, cp.async 3-tap B groups ========
__global__ void __launch_bounds__(256, 2) conv3_mma_kernel(const float* __restrict__ in,
                                                           const uint32_t* __restrict__ wsrc,
                                                           const float* __restrict__ bias,
                                                           float* __restrict__ out) {
    extern __shared__ uint32_t smem32[];
    uint32_t* P = smem32;                    // 9792 words
    uint32_t sbase = smem_u32(smem32);
    const uint32_t BBYTE = 9792u * 4u;       // byte offset of B buffers (2 x 21504 B)

    int tid = threadIdx.x, wid = tid >> 5, lane = tid & 31;
    int z = blockIdx.x >> 3, yt = blockIdx.x & 7;
    int y0 = yt * 4;
    int co0 = blockIdx.y * 112;

    int wm = wid >> 1, wn = wid & 1;         // wm = local y row
    int r4 = lane >> 2, c4 = lane & 3;

    int sub = lane >> 3, l7 = lane & 7;
    int a_lro = ((sub & 1) << 3) + l7;
    int a_sh = sub >> 1;
    int b_segbit = sub & 1;
    int b_ntoff = sub >> 1;
    uint32_t bco[4]; int bsw[4];
#pragma unroll
    for (int t = 0; t < 3; t++) {
        int co = wn * 56 + (2 * t + b_ntoff) * 8 + l7;
        bco[t] = (uint32_t)(co << 6);
        bsw[t] = (co >> 1) & 3;
    }
    {
        int co = wn * 56 + 48 + l7;
        bco[3] = (uint32_t)(co << 6);
        bsw[3] = (co >> 1) & 3;
    }

    float acc[2][7][4];
#pragma unroll
    for (int a = 0; a < 2; a++)
#pragma unroll
        for (int b = 0; b < 7; b++)
#pragma unroll
            for (int c = 0; c < 4; c++) acc[a][b][c] = 0.f;

#define PREFETCH_GRP(s_, buf_) do { \
        int cib_ = (s_) / 9, grp_ = (s_) % 9; \
        uint32_t dbase = sbase + BBYTE + (uint32_t)(buf_) * 21504u; \
        _Pragma("unroll") \
        for (int it = 0; it < 6; it++) { \
            int i = tid + it * 256; \
            if (i < 1344) { \
                int tl = i / 448, rem = i - tl * 448; \
                const uint32_t* src = wsrc + (size_t)((grp_ * 3 + tl) * 7 + cib_) * 3584 + co0 * 16 + rem * 4; \
                cp_async16(dbase + (uint32_t)(tl * 7168 + rem * 16), src); \
            } \
        } \
        CP_COMMIT(); \
    } while (0)

    PREFETCH_GRP(0, 0);
    PREFETCH_GRP(1, 1);

    for (int s = 0; s < 63; s++) {
        int cib = s / 9, grp = s - cib * 9;
        int buf = s & 1;

        if (grp == 0) {
            int cig0 = cib * 32;
#pragma unroll 4
            for (int jj = 0; jj < 36; jj++) {
                int p = wid + jj * 8;        // 0..287
                int wword = p & 15;
                int rowid = p >> 4;          // 0..17 (3z x 6y)
                int pz = rowid / 6, py = rowid - pz * 6;
                int gz = z + pz - 1, gy = y0 + py - 1;
                bool rowok = ((unsigned)gz < 32u) && ((unsigned)gy < 32u);
                const float* s0 = in + (size_t)(cig0 + 2 * wword) * V + (gz << 10) + (gy << 5);
#pragma unroll
                for (int q = 0; q < 2; q++) {
                    int px = lane + q * 32;
                    if (px < 34) {
                        int gx = px - 1;
                        bool ok = rowok && ((unsigned)gx < 32u);
                        float v0 = ok ? __ldg(s0 + gx) : 0.f;
                        float v1 = ok ? __ldg(s0 + V + gx) : 0.f;
                        half2 h = __floats2half2_rn(v0, v1);
                        int voxel = rowid * 34 + px;
                        int st = (((wword >> 2) ^ ((voxel >> 1) & 3)) << 2) | (wword & 3);
                        P[voxel * 16 + st] = *(uint32_t*)&h;
                    }
                }
            }
        }

        CP_WAIT1();
        __syncthreads();      // B(buf) ready + patch visible

#pragma unroll
        for (int t = 0; t < 3; t++) {
            int tap = grp * 3 + t;
            int dz = tap / 9, rem = tap - dz * 9;
            int dy = rem / 3, dx = rem - dy * 3;
            int vb = (dz * 6 + wm + dy) * 34 + dx;
            uint32_t Bbb = sbase + BBYTE + (uint32_t)buf * 21504u + (uint32_t)t * 7168u;

#pragma unroll
            for (int ks = 0; ks < 2; ks++) {
                uint32_t af[2][4];
#pragma unroll
                for (int mt = 0; mt < 2; mt++) {
                    int v = vb + a_lro + (mt << 4);
                    uint32_t ad = sbase + (uint32_t)(v << 6)
                                + (uint32_t)((((ks << 1) + a_sh) ^ ((v >> 1) & 3)) << 4);
                    ldsm_x4(af[mt], ad);
                }
                uint32_t bf[7][2];
#pragma unroll
                for (int t2 = 0; t2 < 3; t2++) {
                    uint32_t r[4];
                    uint32_t ad = Bbb + bco[t2] + (uint32_t)((((ks << 1) + b_segbit) ^ bsw[t2]) << 4);
                    ldsm_x4(r, ad);
                    bf[2 * t2][0] = r[0]; bf[2 * t2][1] = r[1];
                    bf[2 * t2 + 1][0] = r[2]; bf[2 * t2 + 1][1] = r[3];
                }
                {
                    uint32_t r2[2];
                    uint32_t ad = Bbb + bco[3] + (uint32_t)((((ks << 1) + b_segbit) ^ bsw[3]) << 4);
                    ldsm_x2(r2, ad);
                    bf[6][0] = r2[0]; bf[6][1] = r2[1];
                }
#pragma unroll
                for (int mt = 0; mt < 2; mt++)
#pragma unroll
                    for (int nt = 0; nt < 7; nt++)
                        mma_f16(acc[mt][nt], af[mt], bf[nt]);
            }
        }

        __syncthreads();
        if (s + 2 < 63) PREFETCH_GRP(s + 2, buf);
    }

    // ---- epilogue ----
    int yg = y0 + wm;
#pragma unroll
    for (int mt = 0; mt < 2; mt++) {
        int x1 = (mt << 4) + r4;
        int pos = (z << 10) + (yg << 5) + x1;
#pragma unroll
        for (int nt = 0; nt < 7; nt++) {
            int c = co0 + wn * 56 + (nt << 3) + (c4 << 1);
            if (c < CC) {
                float bb = bias[c];
                out[(size_t)c * V + pos] = acc[mt][nt][0] + bb;
                out[(size_t)c * V + pos + 8] = acc[mt][nt][2] + bb;
            }
            if (c + 1 < CC) {
                float bb = bias[c + 1];
                out[(size_t)(c + 1) * V + pos] = acc[mt][nt][1] + bb;
                out[(size_t)(c + 1) * V + pos + 8] = acc[mt][nt][3] + bb;
            }
        }
    }
}

// ======================= final 3-channel conv (fp32, 4 channels / iteration) =======================
__global__ void __launch_bounds__(256) conv_out_kernel(const float* __restrict__ in,
                                                       const float* __restrict__ w,
                                                       const float* __restrict__ bias,
                                                       float* __restrict__ out) {
    __shared__ float sp[3264];   // 4 x (4*6*34)
    __shared__ float sw[324];    // 4 x (3 co x 27)
    int tid = threadIdx.x;
    int z0 = (blockIdx.x >> 3) * 2;
    int y0 = (blockIdx.x & 7) * 4;
    int tz = tid >> 7, ty = (tid >> 5) & 3, tx = tid & 31;

    int poff[13]; bool pval[13]; int phalf[13];
#pragma unroll
    for (int k = 0; k < 13; k++) {
        int i = k * 256 + tid;
        int half = i / 816;
        int j = i - half * 816;
        int pz = j / 204, r = j % 204, py = r / 34, px = r % 34;
        int gz = z0 + pz - 1, gy = y0 + py - 1, gx = px - 1;
        pval[k] = (i < 3264) && ((unsigned)gz < 32u) && ((unsigned)gy < 32u) && ((unsigned)gx < 32u);
        poff[k] = (gz << 10) + (gy << 5) + gx;
        phalf[k] = half;
    }

    float acc[3] = {0.f, 0.f, 0.f};
    for (int c = 0; c < 55; c++) {            // quads (4c..4c+3), ci>=219 padded to 0
        __syncthreads();
#pragma unroll
        for (int k = 0; k < 13; k++) {
            int i = k * 256 + tid;
            if (i < 3264) {
                int ch = 4 * c + phalf[k];
                sp[i] = (pval[k] && ch < CC) ? in[(size_t)ch * V + poff[k]] : 0.f;
            }
        }
#pragma unroll
        for (int wpass = 0; wpass < 2; wpass++) {
            int i = tid + wpass * 256;
            if (i < 324) {
                int half = i / 81;
                int t = i - half * 81;
                int ch = 4 * c + half;
                sw[i] = (ch < CC) ? w[((size_t)(t / 27) * CC + ch) * 27 + (t % 27)] : 0.f;
            }
        }
        __syncthreads();
#pragma unroll
        for (int kz = 0; kz < 3; kz++)
#pragma unroll
            for (int ky = 0; ky < 3; ky++) {
                int base = ((tz + kz) * 6 + (ty + ky)) * 34 + tx;
#pragma unroll
                for (int kx = 0; kx < 3; kx++) {
                    int wt = (kz * 3 + ky) * 3 + kx;
                    float v0 = sp[base + kx];
                    float v1 = sp[816 + base + kx];
                    float v2 = sp[1632 + base + kx];
                    float v3 = sp[2448 + base + kx];
#pragma unroll
                    for (int co = 0; co < 3; co++)
                        acc[co] += sw[co * 27 + wt] * v0 + sw[81 + co * 27 + wt] * v1
                                 + sw[162 + co * 27 + wt] * v2 + sw[243 + co * 27 + wt] * v3;
                }
            }
    }
    int p = ((z0 + tz) << 10) + ((y0 + ty) << 5) + tx;
#pragma unroll
    for (int co = 0; co < 3; co++) out[(size_t)co * V + p] = acc[co] + bias[co];
}

// ======================= launch =======================
extern "C" void kernel_launch(void* const* d_in, const int* in_sizes, int n_in,
                              void* d_out, int out_size) {
    (void)in_sizes; (void)n_in; (void)out_size;
    const float* src   = (const float*)d_in[0];
    const float* tgt   = (const float*)d_in[1];
    const float* C     = (const float*)d_in[2];
    const float* up_w  = (const float*)d_in[3];
    const float* c1_w  = (const float*)d_in[5];
    const float* c1_b  = (const float*)d_in[6];
    const float* c2_w  = (const float*)d_in[7];
    const float* c2_b  = (const float*)d_in[8];
    const float* out_w = (const float*)d_in[9];
    const float* out_b = (const float*)d_in[10];
    float* dout = (float*)d_out;

    float *gx = nullptr, *gy = nullptr;
    uint32_t *wh = nullptr, *wh2 = nullptr;
    cudaGetSymbolAddress((void**)&gx, g_x);
    cudaGetSymbolAddress((void**)&gy, g_y);
    cudaGetSymbolAddress((void**)&wh, g_wh);
    cudaGetSymbolAddress((void**)&wh2, g_wh2);

    const int CONV_SMEM = 82176;   // (9792 + 2*5376) uint32 words
    const int UP_SMEM = 85120;     // (4896 + 2*8192) uint32 words
    cudaFuncSetAttribute(conv3_mma_kernel, cudaFuncAttributeMaxDynamicSharedMemorySize, CONV_SMEM);
    cudaFuncSetAttribute(upsample_mma_kernel, cudaFuncAttributeMaxDynamicSharedMemorySize, UP_SMEM);

    // Stage 1: build concat input (224 channels, pads zeroed)
    pad_zero_kernel<<<640, 256>>>();
    copy_kernel<<<2048, 256>>>(tgt, src);
    reorder_wc_kernel<<<5292, 256>>>(c1_w, c2_w);
    reorder_wu_kernel<<<3328, 256>>>(up_w);
    corr_kernel<<<128, 256>>>(tgt, src);
    upsample_mma_kernel<<<dim3(32, 8), 256, UP_SMEM>>>(C);

    // IN + leaky on Cup (channels 155..218 of g_x)
    instnorm_kernel<<<64, 256>>>(gx + (size_t)155 * V);

    // conv1 (fp16 HMMA) + IN + leaky
    conv3_mma_kernel<<<dim3(256, 2), 256, CONV_SMEM>>>(gx, wh, c1_b, gy);
    instnorm_kernel<<<CC, 256>>>(gy);

    // conv2 + IN + leaky -> Cn in d_out[0 .. 219*V)
    conv3_mma_kernel<<<dim3(256, 2), 256, CONV_SMEM>>>(gy, wh2, c2_b, dout);
    instnorm_kernel<<<CC, 256>>>(dout);

    // output conv -> d_out[219*V .. 222*V)
    conv_out_kernel<<<128, 256>>>(dout, out_w, out_b, dout + (size_t)CC * V);
}